// round 12
// baseline (speedup 1.0000x reference)
#include <cuda_runtime.h>
#include <cuda_bf16.h>
#include <cuda_fp16.h>
#include <cstdint>

// Problem constants
#define BHN 64          // B*H
#define TT 1024         // sequence length
#define DD 128          // head dim
static __device__ __constant__ float INV_TEMP = 0.08838834764831845f;  // 1/sqrt(128)

// ---------------------------------------------------------------------------
// Scratch.
// ---------------------------------------------------------------------------
__device__ __align__(16) unsigned char g_qf[(size_t)BHN * TT * DD * 2];  // [bh][t][d] fp16 (scaled)
__device__ __align__(16) unsigned char g_kf[(size_t)BHN * TT * DD * 2];  // [bh][t][d] fp16
__device__ __align__(16) unsigned char g_vf[(size_t)BHN * DD * TT * 2];  // [bh][d][t] fp16
__device__ __align__(16) unsigned char g_fh[(size_t)BHN * DD * DD * 2];  // [bh][e][d] bf16 hi
__device__ __align__(16) unsigned char g_fl[(size_t)BHN * DD * DD * 2];  // bf16 lo
__device__ __align__(16) unsigned char g_ef[(size_t)BHN * TT * TT * 2];  // [bh][t][s] fp16 unnorm E

typedef unsigned long long u64t;

// ---------------------------------------------------------------------------
// helpers
// ---------------------------------------------------------------------------
__device__ __forceinline__ uint32_t smem_u32(const void* p) {
    uint32_t a;
    asm("{ .reg .u64 t; cvta.to.shared.u64 t, %1; cvt.u32.u64 %0, t; }" : "=r"(a) : "l"(p));
    return a;
}
__device__ __forceinline__ uint32_t pack_bf2(float lo, float hi) {
    uint32_t r;
    asm("cvt.rn.bf16x2.f32 %0, %1, %2;" : "=r"(r) : "f"(hi), "f"(lo));
    return r;
}
__device__ __forceinline__ uint32_t pack_f16(float lo, float hi) {
    uint32_t r;
    asm("cvt.rn.f16x2.f32 %0, %1, %2;" : "=r"(r) : "f"(hi), "f"(lo));
    return r;
}
__device__ __forceinline__ void split2(float v0, float v1, uint32_t& hp, uint32_t& lp) {
    hp = pack_bf2(v0, v1);
    float h0 = __uint_as_float(hp << 16);
    float h1 = __uint_as_float(hp & 0xFFFF0000u);
    lp = pack_bf2(v0 - h0, v1 - h1);
}
__device__ __forceinline__ void ldsm4(uint32_t addr, uint32_t r[4]) {
    asm volatile("ldmatrix.sync.aligned.m8n8.x4.shared.b16 {%0,%1,%2,%3}, [%4];"
        : "=r"(r[0]), "=r"(r[1]), "=r"(r[2]), "=r"(r[3]) : "r"(addr));
}
__device__ __forceinline__ void mma16816(float c[4], const uint32_t a[4],
                                         uint32_t b0, uint32_t b1) {
    asm volatile("mma.sync.aligned.m16n8k16.row.col.f32.bf16.bf16.f32 "
        "{%0,%1,%2,%3}, {%4,%5,%6,%7}, {%8,%9}, {%0,%1,%2,%3};"
        : "+f"(c[0]), "+f"(c[1]), "+f"(c[2]), "+f"(c[3])
        : "r"(a[0]), "r"(a[1]), "r"(a[2]), "r"(a[3]), "r"(b0), "r"(b1));
}
__device__ __forceinline__ void mma16816h(float c[4], const uint32_t a[4],
                                          uint32_t b0, uint32_t b1) {
    asm volatile("mma.sync.aligned.m16n8k16.row.col.f32.f16.f16.f32 "
        "{%0,%1,%2,%3}, {%4,%5,%6,%7}, {%8,%9}, {%0,%1,%2,%3};"
        : "+f"(c[0]), "+f"(c[1]), "+f"(c[2]), "+f"(c[3])
        : "r"(a[0]), "r"(a[1]), "r"(a[2]), "r"(a[3]), "r"(b0), "r"(b1));
}
__device__ __forceinline__ void cpasync16(uint32_t dst, const void* src) {
    asm volatile("cp.async.cg.shared.global [%0], [%1], 16;" :: "r"(dst), "l"(src));
}
#define CP_COMMIT() asm volatile("cp.async.commit_group;" ::: "memory")
#define CP_WAIT3()  asm volatile("cp.async.wait_group 3;" ::: "memory")
#define CP_WAIT2()  asm volatile("cp.async.wait_group 2;" ::: "memory")
#define CP_WAIT0()  asm volatile("cp.async.wait_group 0;" ::: "memory")

// TILE128: [rows][128 halves], row 256B, 16x16B chunks, ch ^= row&7 (low 3 bits).
__device__ __forceinline__ uint32_t a128(uint32_t base, int fr, int ksi,
                                         int rA, int xr, int kq) {
    return base + (uint32_t)((fr + rA) * 256 + (((ksi * 2 + kq) ^ xr) << 4));
}
__device__ __forceinline__ uint32_t SWZ128(int row, int k) {
    return (uint32_t)(row * 256 + ((((k >> 3) ^ (row & 7)) << 4)) + ((k & 7) << 1));
}

// loader: TILE128, 128 rows (1024-thread blocks), gmem row stride in bytes
__device__ __forceinline__ void ld_t128_1024(uint32_t dst, const unsigned char* src,
                                             int stride, int tid) {
    #pragma unroll
    for (int i = 0; i < 2; i++) {
        int idx = i * 1024 + tid;
        int row = idx >> 4, ch = idx & 15;
        cpasync16(dst + row * 256 + (((ch ^ (row & 7)) & 15) << 4),
                  src + (size_t)row * stride + ch * 16);
    }
}

// ---------------------------------------------------------------------------
// Prep kernels
// ---------------------------------------------------------------------------
__global__ void qk_f16_kernel(const float* __restrict__ q, const float* __restrict__ k) {
    const bool isq = (blockIdx.y == 0);
    const float* src = isq ? q : k;
    unsigned char* dst = isq ? g_qf : g_kf;
    const float scale = isq ? INV_TEMP : 1.0f;
    size_t i4 = (size_t)blockIdx.x * 256 + threadIdx.x;
    float4 v = ((const float4*)src)[i4];
    v.x *= scale; v.y *= scale; v.z *= scale; v.w *= scale;
    ((uint2*)dst)[i4] = make_uint2(pack_f16(v.x, v.y), pack_f16(v.z, v.w));
}

__global__ void v_f16_T_kernel(const float* __restrict__ v) {
    __shared__ float tile[32][33];
    const int t0 = blockIdx.x * 32;
    const int bh = blockIdx.y;
    const float* src = v + (size_t)bh * TT * DD;
    unsigned char* dv = g_vf + (size_t)bh * DD * TT * 2;
    const int tid = threadIdx.x;
    for (int d0 = 0; d0 < DD; d0 += 32) {
        #pragma unroll
        for (int i = 0; i < 4; i++) {
            int idx = i * 256 + tid;
            int r = idx >> 5, c = idx & 31;
            tile[r][c] = src[(size_t)(t0 + r) * DD + d0 + c];
        }
        __syncthreads();
        #pragma unroll
        for (int i = 0; i < 2; i++) {
            int idx = i * 256 + tid;
            int r = idx >> 4, c2 = (idx & 15) * 2;
            uint32_t p = pack_f16(tile[c2][r], tile[c2 + 1][r]);
            *(uint32_t*)(dv + ((size_t)(d0 + r) * TT + t0 + c2) * 2) = p;
        }
        __syncthreads();
    }
}

__global__ void ft_split_T_kernel(const float* __restrict__ af) {
    __shared__ float tile[32][33];
    const int e0 = blockIdx.x * 32;
    const int bh = blockIdx.y;
    const float* src = af + (size_t)bh * DD * DD;
    unsigned char* dh = g_fh + (size_t)bh * DD * DD * 2;
    unsigned char* dl = g_fl + (size_t)bh * DD * DD * 2;
    const int tid = threadIdx.x;
    for (int d0 = 0; d0 < DD; d0 += 32) {
        #pragma unroll
        for (int i = 0; i < 4; i++) {
            int idx = i * 256 + tid;
            int r = idx >> 5, c = idx & 31;
            tile[r][c] = src[(size_t)(d0 + r) * DD + e0 + c];
        }
        __syncthreads();
        #pragma unroll
        for (int i = 0; i < 2; i++) {
            int idx = i * 256 + tid;
            int r = idx >> 4, c2 = (idx & 15) * 2;
            float v0 = tile[c2][r], v1 = tile[c2 + 1][r];
            uint32_t hp, lp;
            split2(v0, v1, hp, lp);
            size_t off = ((size_t)(e0 + r) * DD + d0 + c2) * 2;
            *(uint32_t*)(dh + off) = hp;
            *(uint32_t*)(dl + off) = lp;
        }
        __syncthreads();
    }
}

// ---------------------------------------------------------------------------
// Feature attention (CUDA-core f32x2; not the bottleneck)
// ---------------------------------------------------------------------------
__device__ __forceinline__ u64t pk2(float lo, float hi) {
    u64t r; asm("mov.b64 %0, {%1, %2};" : "=l"(r) : "f"(lo), "f"(hi)); return r;
}
__device__ __forceinline__ void fma2(u64t& d, u64t a, u64t b) {
    asm("fma.rn.f32x2 %0, %1, %2, %0;" : "+l"(d) : "l"(a), "l"(b));
}
__device__ __forceinline__ void up2(u64t v, float& a, float& b) {
    asm("mov.b64 {%0, %1}, %2;" : "=f"(a), "=f"(b) : "l"(v));
}

__global__ void __launch_bounds__(256) feature_attn_kernel(
    const float* __restrict__ qf, const float* __restrict__ kf,
    float* __restrict__ attn_f) {
    __shared__ float qs[32 * 34];
    __shared__ float ks[32 * 132];
    __shared__ float Sf[32 * 132];

    const int bh = blockIdx.y;
    const int d0blk = blockIdx.x * 32;
    const float* q = qf + (size_t)bh * TT * DD;
    const float* k = kf + (size_t)bh * TT * DD;
    const int tid = threadIdx.x;
    const int ty = tid >> 4, tx = tid & 15;
    const int r0 = ty * 2;
    const int e0 = tx * 8;

    u64t acc[2][4];
    #pragma unroll
    for (int i = 0; i < 2; i++)
        #pragma unroll
        for (int j = 0; j < 4; j++) acc[i][j] = 0ull;

    for (int tt = 0; tt < TT; tt += 32) {
        #pragma unroll
        for (int i = 0; i < 4; i++) {
            int idx = i * 256 + tid;
            int r = idx >> 5, c = idx & 31;
            qs[r * 34 + c] = q[(size_t)(tt + r) * DD + d0blk + c] * INV_TEMP;
        }
        #pragma unroll
        for (int i = 0; i < 4; i++) {
            int idx = i * 256 + tid;
            int r = idx >> 5, c4 = (idx & 31) * 4;
            *(float4*)&ks[r * 132 + c4] = *(const float4*)&k[(size_t)(tt + r) * DD + c4];
        }
        __syncthreads();
        #pragma unroll 4
        for (int t = 0; t < 32; t++) {
            float2 a = *(float2*)&qs[t * 34 + r0];
            ulonglong2 b0 = *(ulonglong2*)&ks[t * 132 + e0];
            ulonglong2 b1 = *(ulonglong2*)&ks[t * 132 + e0 + 4];
            u64t a0 = pk2(a.x, a.x), a1 = pk2(a.y, a.y);
            fma2(acc[0][0], a0, b0.x); fma2(acc[0][1], a0, b0.y);
            fma2(acc[0][2], a0, b1.x); fma2(acc[0][3], a0, b1.y);
            fma2(acc[1][0], a1, b0.x); fma2(acc[1][1], a1, b0.y);
            fma2(acc[1][2], a1, b1.x); fma2(acc[1][3], a1, b1.y);
        }
        __syncthreads();
    }

    #pragma unroll
    for (int i = 0; i < 2; i++) {
        float x[8];
        up2(acc[i][0], x[0], x[1]); up2(acc[i][1], x[2], x[3]);
        up2(acc[i][2], x[4], x[5]); up2(acc[i][3], x[6], x[7]);
        *(float4*)&Sf[(r0 + i) * 132 + e0]     = make_float4(x[0], x[1], x[2], x[3]);
        *(float4*)&Sf[(r0 + i) * 132 + e0 + 4] = make_float4(x[4], x[5], x[6], x[7]);
    }
    __syncthreads();

    const int lane = tid & 31, w = tid >> 5;
    float* af = attn_f + (size_t)bh * DD * DD;
    #pragma unroll
    for (int rr = 0; rr < 4; rr++) {
        int r = w * 4 + rr;
        float vv[4], mx = -1e30f;
        #pragma unroll
        for (int kk = 0; kk < 4; kk++) {
            vv[kk] = Sf[r * 132 + lane + 32 * kk];
            mx = fmaxf(mx, vv[kk]);
        }
        #pragma unroll
        for (int o = 16; o; o >>= 1) mx = fmaxf(mx, __shfl_xor_sync(~0u, mx, o));
        float ssum = 0.f;
        #pragma unroll
        for (int kk = 0; kk < 4; kk++) { vv[kk] = __expf(vv[kk] - mx); ssum += vv[kk]; }
        #pragma unroll
        for (int o = 16; o; o >>= 1) ssum += __shfl_xor_sync(~0u, ssum, o);
        float iv = 1.0f / ssum;
        #pragma unroll
        for (int kk = 0; kk < 4; kk++)
            af[(size_t)(d0blk + r) * DD + lane + 32 * kk] = vv[kk] * iv;
    }
}

// ---------------------------------------------------------------------------
// Fused time kernel: 8 chunks of 128 cols, 3 syncs/chunk, V triple-buffered.
// per chunk: MMA1 scores (fp16) -> exp -> E fp16 to gmem scratch + smem
// -> MMA2 tv += E@V (fp16).  Tail: GEMM3 (split-bf16) + normalize attn_t
// from fp16 E scratch.
// grid (8, 64), block 1024 (32 warps, warp grid 8x4).
// ---------------------------------------------------------------------------
#define SM_Q   0            // Q fp16 TILE128, 32K
#define SM_K   32768        // 2 bufs x 32K fp16 (128 t x 128 d)
#define SM_V   98304        // 3 bufs x 32K fp16 (128 d x 128 t)
#define SM_E   196608       // 32K fp16 (128 t x 128 s)
// tail overlays:
#define SM_TV  0            // tv split-bf16: hi @0, lo @32768
#define SM_F   65536        // F^T split-bf16: hi @65536, lo @98304
#define SM_RED 229376
#define SM_INV 229888
#define F_SMEM 230400

__global__ void __launch_bounds__(1024, 1) fused_time_kernel(
    float* __restrict__ out, float* __restrict__ attn_t) {
    extern __shared__ char sm[];
    const uint32_t sb = smem_u32(sm);
    float* red  = (float*)(sm + SM_RED);
    float* invs = (float*)(sm + SM_INV);

    const int bh = blockIdx.y;
    const int r0 = blockIdx.x * 128;
    const int tid = threadIdx.x;
    const int wid = tid >> 5, lane = tid & 31;
    const int wm = wid & 7, wn = wid >> 3;        // warp grid 8x4
    const int g = lane >> 2, tig = lane & 3;
    const int rA = (lane & 7) + ((lane >> 3) & 1) * 8;
    const int xr = rA & 7, kq = lane >> 4;
    const int fr = wm * 16;

    if (tid < 128) red[tid] = 0.f;

    const unsigned char* qp = g_qf + ((size_t)bh * TT + r0) * 256;
    const unsigned char* kp = g_kf + (size_t)bh * TT * 256;
    const unsigned char* vf = g_vf + (size_t)bh * DD * 2048;
    unsigned char* efb = g_ef + ((size_t)bh * TT + r0) * 2048;
    float* at = attn_t + ((size_t)bh * TT + r0) * TT;

    // prologue: g1{Q,K0,V0} g2{K1} g3{V1}
    ld_t128_1024(sb + SM_Q, qp, 256, tid);
    ld_t128_1024(sb + SM_K, kp, 256, tid);
    ld_t128_1024(sb + SM_V, vf, 2048, tid);
    CP_COMMIT();
    ld_t128_1024(sb + SM_K + 32768, kp + 128 * 256, 256, tid);
    CP_COMMIT();
    ld_t128_1024(sb + SM_V + 32768, vf + 256, 2048, tid);
    CP_COMMIT();
    CP_WAIT2();                   // g1 done
    __syncthreads();

    float rsum[2] = {0, 0};
    float acc2[4][4];
    #pragma unroll
    for (int j = 0; j < 4; j++)
        #pragma unroll
        for (int i = 0; i < 4; i++) acc2[j][i] = 0.f;

    for (int c = 0; c < 8; c++) {
        const uint32_t kb = sb + SM_K + (c & 1) * 32768;
        const uint32_t vb = sb + SM_V + (c % 3) * 32768;

        // ---- MMA1: scores (128 x 128), fp16, warp tile 16x32 ----
        float acc1[4][4];
        #pragma unroll
        for (int j = 0; j < 4; j++)
            #pragma unroll
            for (int i = 0; i < 4; i++) acc1[j][i] = 0.f;

        #pragma unroll
        for (int ksi = 0; ksi < 8; ksi++) {
            uint32_t aq[4], b0[4], b1[4];
            ldsm4(a128(sb + SM_Q, fr, ksi, rA, xr, kq), aq);
            {
                int nr = wn * 32;
                ldsm4(a128(kb, nr, ksi, rA, xr, kq), b0);
                ldsm4(a128(kb, nr + 16, ksi, rA, xr, kq), b1);
            }
            mma16816h(acc1[0], aq, b0[0], b0[2]);
            mma16816h(acc1[1], aq, b0[1], b0[3]);
            mma16816h(acc1[2], aq, b1[0], b1[2]);
            mma16816h(acc1[3], aq, b1[1], b1[3]);
        }
        __syncthreads();          // A: K(c) buf free; E free (MMA2(c-1) done)

        // prefetch K(c+2) into Kbuf(c&1)  (uniform commit)
        if (c < 6)
            ld_t128_1024(sb + SM_K + (c & 1) * 32768, kp + (size_t)(c + 2) * 128 * 256, 256, tid);
        CP_COMMIT();

        // ---- epilogue: exp -> E fp16 (gmem scratch + smem) + rowsums ----
        {
            const int row = fr + g;
            #pragma unroll
            for (int j = 0; j < 4; j++) {
                float e0 = __expf(acc1[j][0]);
                float e1 = __expf(acc1[j][1]);
                float e2 = __expf(acc1[j][2]);
                float e3 = __expf(acc1[j][3]);
                rsum[0] += e0 + e1;
                rsum[1] += e2 + e3;
                int col = wn * 32 + j * 8 + tig * 2;
                uint32_t pA = pack_f16(e0, e1);
                uint32_t pB = pack_f16(e2, e3);
                *(uint32_t*)(efb + (size_t)row * 2048 + (c * 128 + col) * 2)       = pA;
                *(uint32_t*)(efb + (size_t)(row + 8) * 2048 + (c * 128 + col) * 2) = pB;
                *(uint32_t*)(sm + SM_E + SWZ128(row, col))     = pA;
                *(uint32_t*)(sm + SM_E + SWZ128(row + 8, col)) = pB;
            }
        }
        CP_WAIT3();               // V(c) done (newer: K(c+1), V(c+1), K(c+2))
        __syncthreads();          // B: E + V(c) visible

        // ---- MMA2: tv += E @ V[c]  (fp16, k=128), warp tile 16x32 ----
        #pragma unroll
        for (int ksi = 0; ksi < 8; ksi++) {
            uint32_t ae[4], b0[4], b1[4];
            ldsm4(a128(sb + SM_E, fr, ksi, rA, xr, kq), ae);
            {
                int nr = wn * 32;
                ldsm4(a128(vb, nr, ksi, rA, xr, kq), b0);
                ldsm4(a128(vb, nr + 16, ksi, rA, xr, kq), b1);
            }
            mma16816h(acc2[0], ae, b0[0], b0[2]);
            mma16816h(acc2[1], ae, b0[1], b0[3]);
            mma16816h(acc2[2], ae, b1[0], b1[2]);
            mma16816h(acc2[3], ae, b1[1], b1[3]);
        }

        // prefetch V(c+2) into Vbuf((c+2)%3) — not in use (uniform commit)
        if (c < 6)
            ld_t128_1024(sb + SM_V + ((c + 2) % 3) * 32768, vf + (c + 2) * 256, 2048, tid);
        CP_COMMIT();

        CP_WAIT3();               // K(c+1) done (newer: V(c+1), K(c+2), V(c+2))
        __syncthreads();          // C: K(c+1) visible; MMA2 done -> E, V(c) free
    }

    // ---- rowsums -> invs ----
    rsum[0] += __shfl_xor_sync(~0u, rsum[0], 1);
    rsum[0] += __shfl_xor_sync(~0u, rsum[0], 2);
    rsum[1] += __shfl_xor_sync(~0u, rsum[1], 1);
    rsum[1] += __shfl_xor_sync(~0u, rsum[1], 2);
    if (tig == 0) {
        atomicAdd(&red[fr + g],     rsum[0]);
        atomicAdd(&red[fr + g + 8], rsum[1]);
    }
    __syncthreads();
    if (tid < 128) invs[tid] = 1.0f / red[tid];
    __syncthreads();

    // ---- F^T loads while we stage tv + normalize attn_t ----
    {
        const unsigned char* fhb = g_fh + (size_t)bh * DD * 256;
        const unsigned char* flb = g_fl + (size_t)bh * DD * 256;
        ld_t128_1024(sb + SM_F,         fhb, 256, tid);
        ld_t128_1024(sb + SM_F + 32768, flb, 256, tid);
        CP_COMMIT();
    }
    // stage tv split-bf16 into TV region
    {
        const int row = fr + g;
        #pragma unroll
        for (int j = 0; j < 4; j++) {
            int d0v = wn * 32 + j * 8 + tig * 2;
            uint32_t hp, lp;
            split2(acc2[j][0], acc2[j][1], hp, lp);
            *(uint32_t*)(sm + SM_TV + SWZ128(row, d0v)) = hp;
            *(uint32_t*)(sm + SM_TV + 32768 + SWZ128(row, d0v)) = lp;
            split2(acc2[j][2], acc2[j][3], hp, lp);
            *(uint32_t*)(sm + SM_TV + SWZ128(row + 8, d0v)) = hp;
            *(uint32_t*)(sm + SM_TV + 32768 + SWZ128(row + 8, d0v)) = lp;
        }
    }
    // normalize: read fp16 E scratch (L2-hot), write attn_t f32 once
    #pragma unroll 2
    for (int it = 0; it < 16; it++) {
        int idx = it * 1024 + tid;
        int row = idx >> 7;
        int cb = (idx & 127) * 8;
        float iv = invs[row];
        uint4 hv = *(const uint4*)(efb + (size_t)row * 2048 + cb * 2);
        float2 f0 = __half22float2(*(__half2*)&hv.x);
        float2 f1 = __half22float2(*(__half2*)&hv.y);
        float2 f2 = __half22float2(*(__half2*)&hv.z);
        float2 f3 = __half22float2(*(__half2*)&hv.w);
        *(float4*)&at[(size_t)row * TT + cb] =
            make_float4(f0.x * iv, f0.y * iv, f1.x * iv, f1.y * iv);
        *(float4*)&at[(size_t)row * TT + cb + 4] =
            make_float4(f2.x * iv, f2.y * iv, f3.x * iv, f3.y * iv);
    }
    CP_WAIT0();
    __syncthreads();

    // ---- GEMM3: out = (tv @ F^T) * inv  (split-bf16) ----
    float acc3[4][4];
    #pragma unroll
    for (int j = 0; j < 4; j++)
        #pragma unroll
        for (int i = 0; i < 4; i++) acc3[j][i] = 0.f;

    #pragma unroll
    for (int ksi = 0; ksi < 8; ksi++) {
        uint32_t ah[4], al[4], b0h[4], b1h[4], b0l[4], b1l[4];
        ldsm4(a128(sb + SM_TV, fr, ksi, rA, xr, kq), ah);
        ldsm4(a128(sb + SM_TV + 32768, fr, ksi, rA, xr, kq), al);
        {
            int nr = wn * 32;
            ldsm4(a128(sb + SM_F, nr, ksi, rA, xr, kq), b0h);
            ldsm4(a128(sb + SM_F, nr + 16, ksi, rA, xr, kq), b1h);
            ldsm4(a128(sb + SM_F + 32768, nr, ksi, rA, xr, kq), b0l);
            ldsm4(a128(sb + SM_F + 32768, nr + 16, ksi, rA, xr, kq), b1l);
        }
        mma16816(acc3[0], ah, b0h[0], b0h[2]);
        mma16816(acc3[1], ah, b0h[1], b0h[3]);
        mma16816(acc3[2], ah, b1h[0], b1h[2]);
        mma16816(acc3[3], ah, b1h[1], b1h[3]);
        mma16816(acc3[0], ah, b0l[0], b0l[2]);
        mma16816(acc3[1], ah, b0l[1], b0l[3]);
        mma16816(acc3[2], ah, b1l[0], b1l[2]);
        mma16816(acc3[3], ah, b1l[1], b1l[3]);
        mma16816(acc3[0], al, b0h[0], b0h[2]);
        mma16816(acc3[1], al, b0h[1], b0h[3]);
        mma16816(acc3[2], al, b1h[0], b1h[2]);
        mma16816(acc3[3], al, b1h[1], b1h[3]);
    }

    float* op = out + ((size_t)bh * TT + r0) * DD;
    {
        const int row = fr + g;
        float iva = invs[row];
        float ivb = invs[row + 8];
        #pragma unroll
        for (int j = 0; j < 4; j++) {
            int e = wn * 32 + j * 8 + tig * 2;
            *(float2*)&op[(size_t)row * DD + e] =
                make_float2(acc3[j][0] * iva, acc3[j][1] * iva);
            *(float2*)&op[(size_t)(row + 8) * DD + e] =
                make_float2(acc3[j][2] * ivb, acc3[j][3] * ivb);
        }
    }
}

// ---------------------------------------------------------------------------
// Launch
// ---------------------------------------------------------------------------
extern "C" void kernel_launch(void* const* d_in, const int* in_sizes, int n_in,
                              void* d_out, int out_size) {
    const float* q_time    = (const float*)d_in[0];
    const float* k_time    = (const float*)d_in[1];
    const float* q_feature = (const float*)d_in[2];
    const float* k_feature = (const float*)d_in[3];
    const float* v         = (const float*)d_in[4];

    float* out    = (float*)d_out;                       // [BH][T][D]
    float* attn_t = out + (size_t)BHN * TT * DD;         // [BH][T][T]
    float* attn_f = attn_t + (size_t)BHN * TT * TT;      // [BH][D][D]

    cudaFuncSetAttribute(fused_time_kernel,
                         cudaFuncAttributeMaxDynamicSharedMemorySize, F_SMEM);

    qk_f16_kernel<<<dim3(8192, 2), 256>>>(q_time, k_time);
    v_f16_T_kernel<<<dim3(32, BHN), 256>>>(v);
    feature_attn_kernel<<<dim3(4, BHN), 256>>>(q_feature, k_feature, attn_f);
    ft_split_T_kernel<<<dim3(4, BHN), 256>>>(attn_f);
    fused_time_kernel<<<dim3(8, BHN), 1024, F_SMEM>>>(out, attn_t);
}

// round 13
// speedup vs baseline: 1.0481x; 1.0481x over previous
#include <cuda_runtime.h>
#include <cuda_bf16.h>
#include <cuda_fp16.h>
#include <cstdint>

// Problem constants
#define BHN 64          // B*H
#define TT 1024         // sequence length
#define DD 128          // head dim
static __device__ __constant__ float INV_TEMP = 0.08838834764831845f;  // 1/sqrt(128)

// ---------------------------------------------------------------------------
// Scratch.
// ---------------------------------------------------------------------------
__device__ __align__(16) unsigned char g_qf[(size_t)BHN * TT * DD * 2];  // [bh][t][d] fp16 (scaled)
__device__ __align__(16) unsigned char g_kf[(size_t)BHN * TT * DD * 2];  // [bh][t][d] fp16
__device__ __align__(16) unsigned char g_vf[(size_t)BHN * DD * TT * 2];  // [bh][d][t] fp16
__device__ __align__(16) unsigned char g_fh[(size_t)BHN * DD * DD * 2];  // [bh][e][d] bf16 hi
__device__ __align__(16) unsigned char g_fl[(size_t)BHN * DD * DD * 2];  // bf16 lo

typedef unsigned long long u64t;

// ---------------------------------------------------------------------------
// helpers
// ---------------------------------------------------------------------------
__device__ __forceinline__ uint32_t smem_u32(const void* p) {
    uint32_t a;
    asm("{ .reg .u64 t; cvta.to.shared.u64 t, %1; cvt.u32.u64 %0, t; }" : "=r"(a) : "l"(p));
    return a;
}
__device__ __forceinline__ uint32_t pack_bf2(float lo, float hi) {
    uint32_t r;
    asm("cvt.rn.bf16x2.f32 %0, %1, %2;" : "=r"(r) : "f"(hi), "f"(lo));
    return r;
}
__device__ __forceinline__ uint32_t pack_f16(float lo, float hi) {
    uint32_t r;
    asm("cvt.rn.f16x2.f32 %0, %1, %2;" : "=r"(r) : "f"(hi), "f"(lo));
    return r;
}
__device__ __forceinline__ void split2(float v0, float v1, uint32_t& hp, uint32_t& lp) {
    hp = pack_bf2(v0, v1);
    float h0 = __uint_as_float(hp << 16);
    float h1 = __uint_as_float(hp & 0xFFFF0000u);
    lp = pack_bf2(v0 - h0, v1 - h1);
}
__device__ __forceinline__ void ldsm4(uint32_t addr, uint32_t r[4]) {
    asm volatile("ldmatrix.sync.aligned.m8n8.x4.shared.b16 {%0,%1,%2,%3}, [%4];"
        : "=r"(r[0]), "=r"(r[1]), "=r"(r[2]), "=r"(r[3]) : "r"(addr));
}
__device__ __forceinline__ void mma16816(float c[4], const uint32_t a[4],
                                         uint32_t b0, uint32_t b1) {
    asm volatile("mma.sync.aligned.m16n8k16.row.col.f32.bf16.bf16.f32 "
        "{%0,%1,%2,%3}, {%4,%5,%6,%7}, {%8,%9}, {%0,%1,%2,%3};"
        : "+f"(c[0]), "+f"(c[1]), "+f"(c[2]), "+f"(c[3])
        : "r"(a[0]), "r"(a[1]), "r"(a[2]), "r"(a[3]), "r"(b0), "r"(b1));
}
__device__ __forceinline__ void mma16816h(float c[4], const uint32_t a[4],
                                          uint32_t b0, uint32_t b1) {
    asm volatile("mma.sync.aligned.m16n8k16.row.col.f32.f16.f16.f32 "
        "{%0,%1,%2,%3}, {%4,%5,%6,%7}, {%8,%9}, {%0,%1,%2,%3};"
        : "+f"(c[0]), "+f"(c[1]), "+f"(c[2]), "+f"(c[3])
        : "r"(a[0]), "r"(a[1]), "r"(a[2]), "r"(a[3]), "r"(b0), "r"(b1));
}
__device__ __forceinline__ void cpasync16(uint32_t dst, const void* src) {
    asm volatile("cp.async.cg.shared.global [%0], [%1], 16;" :: "r"(dst), "l"(src));
}
#define CP_COMMIT() asm volatile("cp.async.commit_group;" ::: "memory")
#define CP_WAIT2()  asm volatile("cp.async.wait_group 2;" ::: "memory")
#define CP_WAIT0()  asm volatile("cp.async.wait_group 0;" ::: "memory")

// TILE64 : [rows][64 halves], row 128B.  TILE128: [rows][128 halves], row 256B.
__device__ __forceinline__ uint32_t a64(uint32_t base, int fr, int ksi,
                                        int rA, int xr, int kq) {
    return base + (uint32_t)((fr + rA) * 128 + (((ksi * 2 + kq) ^ xr) << 4));
}
__device__ __forceinline__ uint32_t a128(uint32_t base, int fr, int ksi,
                                         int rA, int xr, int kq) {
    return base + (uint32_t)((fr + rA) * 256 + (((ksi * 2 + kq) ^ xr) << 4));
}
__device__ __forceinline__ uint32_t SWZ64(int row, int k) {
    return (uint32_t)(row * 128 + ((((k >> 3) ^ (row & 7)) << 4)) + ((k & 7) << 1));
}
__device__ __forceinline__ uint32_t SWZ128(int row, int k) {
    return (uint32_t)(row * 256 + ((((k >> 3) ^ (row & 7)) << 4)) + ((k & 7) << 1));
}

// loaders (512-thread blocks)
// TILE128, 64 rows (Q tile, K chunk):
__device__ __forceinline__ void ld_t128r64_512(uint32_t dst, const unsigned char* src,
                                               int stride, int tid) {
    #pragma unroll
    for (int i = 0; i < 2; i++) {
        int idx = i * 512 + tid;
        int row = idx >> 4, ch = idx & 15;
        cpasync16(dst + row * 256 + (((ch ^ (row & 7)) & 15) << 4),
                  src + (size_t)row * stride + ch * 16);
    }
}
// TILE64, 128 rows (V chunk):
__device__ __forceinline__ void ld_t64r128_512(uint32_t dst, const unsigned char* src,
                                               int stride, int tid) {
    #pragma unroll
    for (int i = 0; i < 2; i++) {
        int idx = i * 512 + tid;
        int row = idx >> 3, ch = idx & 7;
        cpasync16(dst + row * 128 + ((ch ^ (row & 7)) << 4),
                  src + (size_t)row * stride + ch * 16);
    }
}
// TILE128, 128 rows (F tiles):
__device__ __forceinline__ void ld_t128r128_512(uint32_t dst, const unsigned char* src,
                                                int stride, int tid) {
    #pragma unroll
    for (int i = 0; i < 4; i++) {
        int idx = i * 512 + tid;
        int row = idx >> 4, ch = idx & 15;
        cpasync16(dst + row * 256 + (((ch ^ (row & 7)) & 15) << 4),
                  src + (size_t)row * stride + ch * 16);
    }
}

// ---------------------------------------------------------------------------
// Prep kernels
// ---------------------------------------------------------------------------
__global__ void qk_f16_kernel(const float* __restrict__ q, const float* __restrict__ k) {
    const bool isq = (blockIdx.y == 0);
    const float* src = isq ? q : k;
    unsigned char* dst = isq ? g_qf : g_kf;
    const float scale = isq ? INV_TEMP : 1.0f;
    size_t i4 = (size_t)blockIdx.x * 256 + threadIdx.x;
    float4 v = ((const float4*)src)[i4];
    v.x *= scale; v.y *= scale; v.z *= scale; v.w *= scale;
    ((uint2*)dst)[i4] = make_uint2(pack_f16(v.x, v.y), pack_f16(v.z, v.w));
}

__global__ void v_f16_T_kernel(const float* __restrict__ v) {
    __shared__ float tile[32][33];
    const int t0 = blockIdx.x * 32;
    const int bh = blockIdx.y;
    const float* src = v + (size_t)bh * TT * DD;
    unsigned char* dv = g_vf + (size_t)bh * DD * TT * 2;
    const int tid = threadIdx.x;
    for (int d0 = 0; d0 < DD; d0 += 32) {
        #pragma unroll
        for (int i = 0; i < 4; i++) {
            int idx = i * 256 + tid;
            int r = idx >> 5, c = idx & 31;
            tile[r][c] = src[(size_t)(t0 + r) * DD + d0 + c];
        }
        __syncthreads();
        #pragma unroll
        for (int i = 0; i < 2; i++) {
            int idx = i * 256 + tid;
            int r = idx >> 4, c2 = (idx & 15) * 2;
            uint32_t p = pack_f16(tile[c2][r], tile[c2 + 1][r]);
            *(uint32_t*)(dv + ((size_t)(d0 + r) * TT + t0 + c2) * 2) = p;
        }
        __syncthreads();
    }
}

__global__ void ft_split_T_kernel(const float* __restrict__ af) {
    __shared__ float tile[32][33];
    const int e0 = blockIdx.x * 32;
    const int bh = blockIdx.y;
    const float* src = af + (size_t)bh * DD * DD;
    unsigned char* dh = g_fh + (size_t)bh * DD * DD * 2;
    unsigned char* dl = g_fl + (size_t)bh * DD * DD * 2;
    const int tid = threadIdx.x;
    for (int d0 = 0; d0 < DD; d0 += 32) {
        #pragma unroll
        for (int i = 0; i < 4; i++) {
            int idx = i * 256 + tid;
            int r = idx >> 5, c = idx & 31;
            tile[r][c] = src[(size_t)(d0 + r) * DD + e0 + c];
        }
        __syncthreads();
        #pragma unroll
        for (int i = 0; i < 2; i++) {
            int idx = i * 256 + tid;
            int r = idx >> 4, c2 = (idx & 15) * 2;
            float v0 = tile[c2][r], v1 = tile[c2 + 1][r];
            uint32_t hp, lp;
            split2(v0, v1, hp, lp);
            size_t off = ((size_t)(e0 + r) * DD + d0 + c2) * 2;
            *(uint32_t*)(dh + off) = hp;
            *(uint32_t*)(dl + off) = lp;
        }
        __syncthreads();
    }
}

// ---------------------------------------------------------------------------
// Feature attention (CUDA-core f32x2; not the bottleneck)
// ---------------------------------------------------------------------------
__device__ __forceinline__ u64t pk2(float lo, float hi) {
    u64t r; asm("mov.b64 %0, {%1, %2};" : "=l"(r) : "f"(lo), "f"(hi)); return r;
}
__device__ __forceinline__ void fma2(u64t& d, u64t a, u64t b) {
    asm("fma.rn.f32x2 %0, %1, %2, %0;" : "+l"(d) : "l"(a), "l"(b));
}
__device__ __forceinline__ void up2(u64t v, float& a, float& b) {
    asm("mov.b64 {%0, %1}, %2;" : "=f"(a), "=f"(b) : "l"(v));
}

__global__ void __launch_bounds__(256) feature_attn_kernel(
    const float* __restrict__ qf, const float* __restrict__ kf,
    float* __restrict__ attn_f) {
    __shared__ float qs[32 * 34];
    __shared__ float ks[32 * 132];
    __shared__ float Sf[32 * 132];

    const int bh = blockIdx.y;
    const int d0blk = blockIdx.x * 32;
    const float* q = qf + (size_t)bh * TT * DD;
    const float* k = kf + (size_t)bh * TT * DD;
    const int tid = threadIdx.x;
    const int ty = tid >> 4, tx = tid & 15;
    const int r0 = ty * 2;
    const int e0 = tx * 8;

    u64t acc[2][4];
    #pragma unroll
    for (int i = 0; i < 2; i++)
        #pragma unroll
        for (int j = 0; j < 4; j++) acc[i][j] = 0ull;

    for (int tt = 0; tt < TT; tt += 32) {
        #pragma unroll
        for (int i = 0; i < 4; i++) {
            int idx = i * 256 + tid;
            int r = idx >> 5, c = idx & 31;
            qs[r * 34 + c] = q[(size_t)(tt + r) * DD + d0blk + c] * INV_TEMP;
        }
        #pragma unroll
        for (int i = 0; i < 4; i++) {
            int idx = i * 256 + tid;
            int r = idx >> 5, c4 = (idx & 31) * 4;
            *(float4*)&ks[r * 132 + c4] = *(const float4*)&k[(size_t)(tt + r) * DD + c4];
        }
        __syncthreads();
        #pragma unroll 4
        for (int t = 0; t < 32; t++) {
            float2 a = *(float2*)&qs[t * 34 + r0];
            ulonglong2 b0 = *(ulonglong2*)&ks[t * 132 + e0];
            ulonglong2 b1 = *(ulonglong2*)&ks[t * 132 + e0 + 4];
            u64t a0 = pk2(a.x, a.x), a1 = pk2(a.y, a.y);
            fma2(acc[0][0], a0, b0.x); fma2(acc[0][1], a0, b0.y);
            fma2(acc[0][2], a0, b1.x); fma2(acc[0][3], a0, b1.y);
            fma2(acc[1][0], a1, b0.x); fma2(acc[1][1], a1, b0.y);
            fma2(acc[1][2], a1, b1.x); fma2(acc[1][3], a1, b1.y);
        }
        __syncthreads();
    }

    #pragma unroll
    for (int i = 0; i < 2; i++) {
        float x[8];
        up2(acc[i][0], x[0], x[1]); up2(acc[i][1], x[2], x[3]);
        up2(acc[i][2], x[4], x[5]); up2(acc[i][3], x[6], x[7]);
        *(float4*)&Sf[(r0 + i) * 132 + e0]     = make_float4(x[0], x[1], x[2], x[3]);
        *(float4*)&Sf[(r0 + i) * 132 + e0 + 4] = make_float4(x[4], x[5], x[6], x[7]);
    }
    __syncthreads();

    const int lane = tid & 31, w = tid >> 5;
    float* af = attn_f + (size_t)bh * DD * DD;
    #pragma unroll
    for (int rr = 0; rr < 4; rr++) {
        int r = w * 4 + rr;
        float vv[4], mx = -1e30f;
        #pragma unroll
        for (int kk = 0; kk < 4; kk++) {
            vv[kk] = Sf[r * 132 + lane + 32 * kk];
            mx = fmaxf(mx, vv[kk]);
        }
        #pragma unroll
        for (int o = 16; o; o >>= 1) mx = fmaxf(mx, __shfl_xor_sync(~0u, mx, o));
        float ssum = 0.f;
        #pragma unroll
        for (int kk = 0; kk < 4; kk++) { vv[kk] = __expf(vv[kk] - mx); ssum += vv[kk]; }
        #pragma unroll
        for (int o = 16; o; o >>= 1) ssum += __shfl_xor_sync(~0u, ssum, o);
        float iv = 1.0f / ssum;
        #pragma unroll
        for (int kk = 0; kk < 4; kk++)
            af[(size_t)(d0blk + r) * DD + lane + 32 * kk] = vv[kk] * iv;
    }
}

// ---------------------------------------------------------------------------
// Fused time kernel: 64-row tiles, 512 threads, 2 CTAs/SM.
// per 64-col chunk: MMA1 scores (fp16) -> exp -> unnorm f32 attn_t + E fp16
// smem -> MMA2 tv += E@V (fp16).  Tail: GEMM3 (split-bf16) + in-place
// normalize of attn_t rows.
// grid (16, 64), block 512 (16 warps, warp grid 4x4).
// ---------------------------------------------------------------------------
#define SM_Q   0            // Q fp16 TILE128 64 rows, 16K
#define SM_K   16384        // 2 bufs x 16K fp16 (64 t x 128 d)
#define SM_V   49152        // 2 bufs x 16K fp16 (128 d x 64 t)
#define SM_E   81920        // 8K fp16 (64 t x 64 s)
// tail overlays:
#define SM_TV  0            // tv split-bf16 64 rows: hi @0 16K, lo @16384
#define SM_F   32768        // F^T split-bf16 128 rows: hi @32768 32K, lo @65536
#define SM_RED 98304
#define SM_INV 98560
#define F_SMEM 98816

__global__ void __launch_bounds__(512, 2) fused_time_kernel(
    float* __restrict__ out, float* __restrict__ attn_t) {
    extern __shared__ char sm[];
    const uint32_t sb = smem_u32(sm);
    float* red  = (float*)(sm + SM_RED);
    float* invs = (float*)(sm + SM_INV);

    const int bh = blockIdx.y;
    const int r0 = blockIdx.x * 64;
    const int tid = threadIdx.x;
    const int wid = tid >> 5, lane = tid & 31;
    const int wm = wid & 3, wn = wid >> 2;        // warp grid 4x4
    const int g = lane >> 2, tig = lane & 3;
    const int rA = (lane & 7) + ((lane >> 3) & 1) * 8;
    const int xr = rA & 7, kq = lane >> 4;
    const int fr = wm * 16;

    if (tid < 64) red[tid] = 0.f;

    const unsigned char* qp = g_qf + ((size_t)bh * TT + r0) * 256;
    const unsigned char* kp = g_kf + (size_t)bh * TT * 256;
    const unsigned char* vf = g_vf + (size_t)bh * DD * 2048;
    float* at = attn_t + ((size_t)bh * TT + r0) * TT;

    // prologue: {Q, K0} | {V0} | {K1}
    ld_t128r64_512(sb + SM_Q, qp, 256, tid);
    ld_t128r64_512(sb + SM_K, kp, 256, tid);
    CP_COMMIT();
    ld_t64r128_512(sb + SM_V, vf, 2048, tid);
    CP_COMMIT();
    ld_t128r64_512(sb + SM_K + 16384, kp + 64 * 256, 256, tid);
    CP_COMMIT();
    CP_WAIT2();                   // {Q,K0} landed
    __syncthreads();

    float rsum[2] = {0, 0};
    float acc2[4][4];
    #pragma unroll
    for (int j = 0; j < 4; j++)
        #pragma unroll
        for (int i = 0; i < 4; i++) acc2[j][i] = 0.f;

    for (int c = 0; c < 16; c++) {
        const uint32_t kb = sb + SM_K + (c & 1) * 16384;
        const uint32_t vb = sb + SM_V + (c & 1) * 16384;

        // ---- MMA1: scores (64 rows x 64 cols), fp16, warp tile 16x16 ----
        float acc1[2][4];
        #pragma unroll
        for (int j = 0; j < 2; j++)
            #pragma unroll
            for (int i = 0; i < 4; i++) acc1[j][i] = 0.f;

        #pragma unroll
        for (int ksi = 0; ksi < 8; ksi++) {
            uint32_t aq[4], bk[4];
            ldsm4(a128(sb + SM_Q, fr, ksi, rA, xr, kq), aq);
            ldsm4(a128(kb, wn * 16, ksi, rA, xr, kq), bk);
            mma16816h(acc1[0], aq, bk[0], bk[2]);
            mma16816h(acc1[1], aq, bk[1], bk[3]);
        }
        __syncthreads();          // K[c] consumed; prev E consumed

        if (c < 15) {             // V[c+1]
            ld_t64r128_512(sb + SM_V + ((c + 1) & 1) * 16384, vf + (c + 1) * 128, 2048, tid);
        }
        CP_COMMIT();

        // ---- epilogue: exp -> unnormalized attn_t + E fp16 smem ----
        {
            const int row = fr + g;
            #pragma unroll
            for (int j = 0; j < 2; j++) {
                float e0 = __expf(acc1[j][0]);
                float e1 = __expf(acc1[j][1]);
                float e2 = __expf(acc1[j][2]);
                float e3 = __expf(acc1[j][3]);
                rsum[0] += e0 + e1;
                rsum[1] += e2 + e3;
                int col = wn * 16 + j * 8 + tig * 2;
                *(float2*)&at[(size_t)row * TT + c * 64 + col]       = make_float2(e0, e1);
                *(float2*)&at[(size_t)(row + 8) * TT + c * 64 + col] = make_float2(e2, e3);
                *(uint32_t*)(sm + SM_E + SWZ64(row, col))     = pack_f16(e0, e1);
                *(uint32_t*)(sm + SM_E + SWZ64(row + 8, col)) = pack_f16(e2, e3);
            }
        }
        CP_WAIT2();               // V[c] landed
        __syncthreads();          // E visible + V[c] visible

        // ---- MMA2: tv += E @ V[c]  (fp16, k=64), warp tile 16x32 ----
        #pragma unroll
        for (int ksi = 0; ksi < 4; ksi++) {
            uint32_t ae[4], b0[4], b1[4];
            ldsm4(a64(sb + SM_E, fr, ksi, rA, xr, kq), ae);
            {
                int nr = wn * 32;
                ldsm4(a64(vb, nr, ksi, rA, xr, kq), b0);
                ldsm4(a64(vb, nr + 16, ksi, rA, xr, kq), b1);
            }
            mma16816h(acc2[0], ae, b0[0], b0[2]);
            mma16816h(acc2[1], ae, b0[1], b0[3]);
            mma16816h(acc2[2], ae, b1[0], b1[2]);
            mma16816h(acc2[3], ae, b1[1], b1[3]);
        }
        __syncthreads();          // V[c] + E consumed

        if (c < 14) {             // K[c+2] into buf (c&1)
            ld_t128r64_512(sb + SM_K + (c & 1) * 16384, kp + (size_t)(c + 2) * 64 * 256, 256, tid);
        }
        CP_COMMIT();
        CP_WAIT2();               // K[c+1] landed
        __syncthreads();
    }

    // ---- rowsums -> invs ----
    rsum[0] += __shfl_xor_sync(~0u, rsum[0], 1);
    rsum[0] += __shfl_xor_sync(~0u, rsum[0], 2);
    rsum[1] += __shfl_xor_sync(~0u, rsum[1], 1);
    rsum[1] += __shfl_xor_sync(~0u, rsum[1], 2);
    if (tig == 0) {
        atomicAdd(&red[fr + g],     rsum[0]);
        atomicAdd(&red[fr + g + 8], rsum[1]);
    }
    __syncthreads();
    if (tid < 64) invs[tid] = 1.0f / red[tid];
    __syncthreads();

    // ---- F^T loads while we stage tv + normalize attn_t ----
    {
        const unsigned char* fhb = g_fh + (size_t)bh * DD * 256;
        const unsigned char* flb = g_fl + (size_t)bh * DD * 256;
        ld_t128r128_512(sb + SM_F,         fhb, 256, tid);
        ld_t128r128_512(sb + SM_F + 32768, flb, 256, tid);
        CP_COMMIT();
    }
    // stage tv split-bf16 into TV region (64 rows TILE128: hi @SM_TV, lo @+16384)
    {
        const int row = fr + g;
        #pragma unroll
        for (int j = 0; j < 4; j++) {
            int d0v = wn * 32 + j * 8 + tig * 2;
            uint32_t hp, lp;
            split2(acc2[j][0], acc2[j][1], hp, lp);
            *(uint32_t*)(sm + SM_TV + SWZ128(row, d0v)) = hp;
            *(uint32_t*)(sm + SM_TV + 16384 + SWZ128(row, d0v)) = lp;
            split2(acc2[j][2], acc2[j][3], hp, lp);
            *(uint32_t*)(sm + SM_TV + SWZ128(row + 8, d0v)) = hp;
            *(uint32_t*)(sm + SM_TV + 16384 + SWZ128(row + 8, d0v)) = lp;
        }
    }
    // normalize attn_t in place (L2-hot; overlaps with F cp.async)
    {
        float4* at4 = (float4*)at;
        #pragma unroll 4
        for (int it = 0; it < 32; it++) {
            int idx = it * 512 + tid;
            int row = idx >> 8, c4 = idx & 255;
            float iv = invs[row];
            float4 vv = at4[(size_t)row * 256 + c4];
            vv.x *= iv; vv.y *= iv; vv.z *= iv; vv.w *= iv;
            at4[(size_t)row * 256 + c4] = vv;
        }
    }
    CP_WAIT0();
    __syncthreads();

    // ---- GEMM3: out = (tv @ F^T) * inv  (split-bf16) ----
    float acc3[4][4];
    #pragma unroll
    for (int j = 0; j < 4; j++)
        #pragma unroll
        for (int i = 0; i < 4; i++) acc3[j][i] = 0.f;

    #pragma unroll
    for (int ksi = 0; ksi < 8; ksi++) {
        uint32_t ah[4], al[4], b0h[4], b1h[4], b0l[4], b1l[4];
        ldsm4(a128(sb + SM_TV, fr, ksi, rA, xr, kq), ah);
        ldsm4(a128(sb + SM_TV + 16384, fr, ksi, rA, xr, kq), al);
        {
            int nr = wn * 32;
            ldsm4(a128(sb + SM_F, nr, ksi, rA, xr, kq), b0h);
            ldsm4(a128(sb + SM_F, nr + 16, ksi, rA, xr, kq), b1h);
            ldsm4(a128(sb + SM_F + 32768, nr, ksi, rA, xr, kq), b0l);
            ldsm4(a128(sb + SM_F + 32768, nr + 16, ksi, rA, xr, kq), b1l);
        }
        mma16816(acc3[0], ah, b0h[0], b0h[2]);
        mma16816(acc3[1], ah, b0h[1], b0h[3]);
        mma16816(acc3[2], ah, b1h[0], b1h[2]);
        mma16816(acc3[3], ah, b1h[1], b1h[3]);
        mma16816(acc3[0], ah, b0l[0], b0l[2]);
        mma16816(acc3[1], ah, b0l[1], b0l[3]);
        mma16816(acc3[2], ah, b1l[0], b1l[2]);
        mma16816(acc3[3], ah, b1l[1], b1l[3]);
        mma16816(acc3[0], al, b0h[0], b0h[2]);
        mma16816(acc3[1], al, b0h[1], b0h[3]);
        mma16816(acc3[2], al, b1h[0], b1h[2]);
        mma16816(acc3[3], al, b1h[1], b1h[3]);
    }

    float* op = out + ((size_t)bh * TT + r0) * DD;
    {
        const int row = fr + g;
        float iva = invs[row];
        float ivb = invs[row + 8];
        #pragma unroll
        for (int j = 0; j < 4; j++) {
            int e = wn * 32 + j * 8 + tig * 2;
            *(float2*)&op[(size_t)row * DD + e] =
                make_float2(acc3[j][0] * iva, acc3[j][1] * iva);
            *(float2*)&op[(size_t)(row + 8) * DD + e] =
                make_float2(acc3[j][2] * ivb, acc3[j][3] * ivb);
        }
    }
}

// ---------------------------------------------------------------------------
// Launch
// ---------------------------------------------------------------------------
extern "C" void kernel_launch(void* const* d_in, const int* in_sizes, int n_in,
                              void* d_out, int out_size) {
    const float* q_time    = (const float*)d_in[0];
    const float* k_time    = (const float*)d_in[1];
    const float* q_feature = (const float*)d_in[2];
    const float* k_feature = (const float*)d_in[3];
    const float* v         = (const float*)d_in[4];

    float* out    = (float*)d_out;                       // [BH][T][D]
    float* attn_t = out + (size_t)BHN * TT * DD;         // [BH][T][T]
    float* attn_f = attn_t + (size_t)BHN * TT * TT;      // [BH][D][D]

    cudaFuncSetAttribute(fused_time_kernel,
                         cudaFuncAttributeMaxDynamicSharedMemorySize, F_SMEM);

    qk_f16_kernel<<<dim3(8192, 2), 256>>>(q_time, k_time);
    v_f16_T_kernel<<<dim3(32, BHN), 256>>>(v);
    feature_attn_kernel<<<dim3(4, BHN), 256>>>(q_feature, k_feature, attn_f);
    ft_split_T_kernel<<<dim3(4, BHN), 256>>>(attn_f);
    fused_time_kernel<<<dim3(16, BHN), 512, F_SMEM>>>(out, attn_t);
}

// round 14
// speedup vs baseline: 1.1054x; 1.0547x over previous
#include <cuda_runtime.h>
#include <cuda_bf16.h>
#include <cuda_fp16.h>
#include <cstdint>

// Problem constants
#define BHN 64          // B*H
#define TT 1024         // sequence length
#define DD 128          // head dim
static __device__ __constant__ float INV_TEMP = 0.08838834764831845f;  // 1/sqrt(128)

// ---------------------------------------------------------------------------
// Scratch.
// ---------------------------------------------------------------------------
__device__ __align__(16) unsigned char g_qf[(size_t)BHN * TT * DD * 2];  // [bh][t][d] fp16 (scaled)
__device__ __align__(16) unsigned char g_kf[(size_t)BHN * TT * DD * 2];  // [bh][t][d] fp16
__device__ __align__(16) unsigned char g_vf[(size_t)BHN * DD * TT * 2];  // [bh][d][t] fp16
__device__ __align__(16) unsigned char g_fh[(size_t)BHN * DD * DD * 2];  // [bh][e][d] bf16 hi
__device__ __align__(16) unsigned char g_fl[(size_t)BHN * DD * DD * 2];  // bf16 lo

typedef unsigned long long u64t;

// ---------------------------------------------------------------------------
// helpers
// ---------------------------------------------------------------------------
__device__ __forceinline__ uint32_t smem_u32(const void* p) {
    uint32_t a;
    asm("{ .reg .u64 t; cvta.to.shared.u64 t, %1; cvt.u32.u64 %0, t; }" : "=r"(a) : "l"(p));
    return a;
}
__device__ __forceinline__ uint32_t pack_bf2(float lo, float hi) {
    uint32_t r;
    asm("cvt.rn.bf16x2.f32 %0, %1, %2;" : "=r"(r) : "f"(hi), "f"(lo));
    return r;
}
__device__ __forceinline__ uint32_t pack_f16(float lo, float hi) {
    uint32_t r;
    asm("cvt.rn.f16x2.f32 %0, %1, %2;" : "=r"(r) : "f"(hi), "f"(lo));
    return r;
}
__device__ __forceinline__ void split2(float v0, float v1, uint32_t& hp, uint32_t& lp) {
    hp = pack_bf2(v0, v1);
    float h0 = __uint_as_float(hp << 16);
    float h1 = __uint_as_float(hp & 0xFFFF0000u);
    lp = pack_bf2(v0 - h0, v1 - h1);
}
__device__ __forceinline__ void ldsm4(uint32_t addr, uint32_t r[4]) {
    asm volatile("ldmatrix.sync.aligned.m8n8.x4.shared.b16 {%0,%1,%2,%3}, [%4];"
        : "=r"(r[0]), "=r"(r[1]), "=r"(r[2]), "=r"(r[3]) : "r"(addr));
}
__device__ __forceinline__ void mma16816(float c[4], const uint32_t a[4],
                                         uint32_t b0, uint32_t b1) {
    asm volatile("mma.sync.aligned.m16n8k16.row.col.f32.bf16.bf16.f32 "
        "{%0,%1,%2,%3}, {%4,%5,%6,%7}, {%8,%9}, {%0,%1,%2,%3};"
        : "+f"(c[0]), "+f"(c[1]), "+f"(c[2]), "+f"(c[3])
        : "r"(a[0]), "r"(a[1]), "r"(a[2]), "r"(a[3]), "r"(b0), "r"(b1));
}
__device__ __forceinline__ void mma16816h(float c[4], const uint32_t a[4],
                                          uint32_t b0, uint32_t b1) {
    asm volatile("mma.sync.aligned.m16n8k16.row.col.f32.f16.f16.f32 "
        "{%0,%1,%2,%3}, {%4,%5,%6,%7}, {%8,%9}, {%0,%1,%2,%3};"
        : "+f"(c[0]), "+f"(c[1]), "+f"(c[2]), "+f"(c[3])
        : "r"(a[0]), "r"(a[1]), "r"(a[2]), "r"(a[3]), "r"(b0), "r"(b1));
}
__device__ __forceinline__ void cpasync16(uint32_t dst, const void* src) {
    asm volatile("cp.async.cg.shared.global [%0], [%1], 16;" :: "r"(dst), "l"(src));
}
#define CP_COMMIT() asm volatile("cp.async.commit_group;" ::: "memory")
#define CP_WAIT2()  asm volatile("cp.async.wait_group 2;" ::: "memory")
#define CP_WAIT1()  asm volatile("cp.async.wait_group 1;" ::: "memory")
#define CP_WAIT0()  asm volatile("cp.async.wait_group 0;" ::: "memory")

// TILE64 : [rows][64 halves], row 128B.  TILE128: [rows][128 halves], row 256B.
__device__ __forceinline__ uint32_t a64(uint32_t base, int fr, int ksi,
                                        int rA, int xr, int kq) {
    return base + (uint32_t)((fr + rA) * 128 + (((ksi * 2 + kq) ^ xr) << 4));
}
__device__ __forceinline__ uint32_t a128(uint32_t base, int fr, int ksi,
                                         int rA, int xr, int kq) {
    return base + (uint32_t)((fr + rA) * 256 + (((ksi * 2 + kq) ^ xr) << 4));
}
__device__ __forceinline__ uint32_t SWZ64(int row, int k) {
    return (uint32_t)(row * 128 + ((((k >> 3) ^ (row & 7)) << 4)) + ((k & 7) << 1));
}
__device__ __forceinline__ uint32_t SWZ128(int row, int k) {
    return (uint32_t)(row * 256 + ((((k >> 3) ^ (row & 7)) << 4)) + ((k & 7) << 1));
}

// loaders (512-thread blocks)
__device__ __forceinline__ void ld_t128r64_512(uint32_t dst, const unsigned char* src,
                                               int stride, int tid) {
    #pragma unroll
    for (int i = 0; i < 2; i++) {
        int idx = i * 512 + tid;
        int row = idx >> 4, ch = idx & 15;
        cpasync16(dst + row * 256 + (((ch ^ (row & 7)) & 15) << 4),
                  src + (size_t)row * stride + ch * 16);
    }
}
__device__ __forceinline__ void ld_t64r128_512(uint32_t dst, const unsigned char* src,
                                               int stride, int tid) {
    #pragma unroll
    for (int i = 0; i < 2; i++) {
        int idx = i * 512 + tid;
        int row = idx >> 3, ch = idx & 7;
        cpasync16(dst + row * 128 + ((ch ^ (row & 7)) << 4),
                  src + (size_t)row * stride + ch * 16);
    }
}
__device__ __forceinline__ void ld_t128r128_512(uint32_t dst, const unsigned char* src,
                                                int stride, int tid) {
    #pragma unroll
    for (int i = 0; i < 4; i++) {
        int idx = i * 512 + tid;
        int row = idx >> 4, ch = idx & 15;
        cpasync16(dst + row * 256 + (((ch ^ (row & 7)) & 15) << 4),
                  src + (size_t)row * stride + ch * 16);
    }
}

// ---------------------------------------------------------------------------
// Prep kernels
// ---------------------------------------------------------------------------
__global__ void qk_f16_kernel(const float* __restrict__ q, const float* __restrict__ k) {
    const bool isq = (blockIdx.y == 0);
    const float* src = isq ? q : k;
    unsigned char* dst = isq ? g_qf : g_kf;
    const float scale = isq ? INV_TEMP : 1.0f;
    size_t i4 = (size_t)blockIdx.x * 256 + threadIdx.x;
    float4 v = ((const float4*)src)[i4];
    v.x *= scale; v.y *= scale; v.z *= scale; v.w *= scale;
    ((uint2*)dst)[i4] = make_uint2(pack_f16(v.x, v.y), pack_f16(v.z, v.w));
}

__global__ void v_f16_T_kernel(const float* __restrict__ v) {
    __shared__ float tile[32][33];
    const int t0 = blockIdx.x * 32;
    const int bh = blockIdx.y;
    const float* src = v + (size_t)bh * TT * DD;
    unsigned char* dv = g_vf + (size_t)bh * DD * TT * 2;
    const int tid = threadIdx.x;
    for (int d0 = 0; d0 < DD; d0 += 32) {
        #pragma unroll
        for (int i = 0; i < 4; i++) {
            int idx = i * 256 + tid;
            int r = idx >> 5, c = idx & 31;
            tile[r][c] = src[(size_t)(t0 + r) * DD + d0 + c];
        }
        __syncthreads();
        #pragma unroll
        for (int i = 0; i < 2; i++) {
            int idx = i * 256 + tid;
            int r = idx >> 4, c2 = (idx & 15) * 2;
            uint32_t p = pack_f16(tile[c2][r], tile[c2 + 1][r]);
            *(uint32_t*)(dv + ((size_t)(d0 + r) * TT + t0 + c2) * 2) = p;
        }
        __syncthreads();
    }
}

__global__ void ft_split_T_kernel(const float* __restrict__ af) {
    __shared__ float tile[32][33];
    const int e0 = blockIdx.x * 32;
    const int bh = blockIdx.y;
    const float* src = af + (size_t)bh * DD * DD;
    unsigned char* dh = g_fh + (size_t)bh * DD * DD * 2;
    unsigned char* dl = g_fl + (size_t)bh * DD * DD * 2;
    const int tid = threadIdx.x;
    for (int d0 = 0; d0 < DD; d0 += 32) {
        #pragma unroll
        for (int i = 0; i < 4; i++) {
            int idx = i * 256 + tid;
            int r = idx >> 5, c = idx & 31;
            tile[r][c] = src[(size_t)(d0 + r) * DD + e0 + c];
        }
        __syncthreads();
        #pragma unroll
        for (int i = 0; i < 2; i++) {
            int idx = i * 256 + tid;
            int r = idx >> 4, c2 = (idx & 15) * 2;
            float v0 = tile[c2][r], v1 = tile[c2 + 1][r];
            uint32_t hp, lp;
            split2(v0, v1, hp, lp);
            size_t off = ((size_t)(e0 + r) * DD + d0 + c2) * 2;
            *(uint32_t*)(dh + off) = hp;
            *(uint32_t*)(dl + off) = lp;
        }
        __syncthreads();
    }
}

// ---------------------------------------------------------------------------
// Feature attention (CUDA-core f32x2; not the bottleneck)
// ---------------------------------------------------------------------------
__device__ __forceinline__ u64t pk2(float lo, float hi) {
    u64t r; asm("mov.b64 %0, {%1, %2};" : "=l"(r) : "f"(lo), "f"(hi)); return r;
}
__device__ __forceinline__ void fma2(u64t& d, u64t a, u64t b) {
    asm("fma.rn.f32x2 %0, %1, %2, %0;" : "+l"(d) : "l"(a), "l"(b));
}
__device__ __forceinline__ void up2(u64t v, float& a, float& b) {
    asm("mov.b64 {%0, %1}, %2;" : "=f"(a), "=f"(b) : "l"(v));
}

__global__ void __launch_bounds__(256) feature_attn_kernel(
    const float* __restrict__ qf, const float* __restrict__ kf,
    float* __restrict__ attn_f) {
    __shared__ float qs[32 * 34];
    __shared__ float ks[32 * 132];
    __shared__ float Sf[32 * 132];

    const int bh = blockIdx.y;
    const int d0blk = blockIdx.x * 32;
    const float* q = qf + (size_t)bh * TT * DD;
    const float* k = kf + (size_t)bh * TT * DD;
    const int tid = threadIdx.x;
    const int ty = tid >> 4, tx = tid & 15;
    const int r0 = ty * 2;
    const int e0 = tx * 8;

    u64t acc[2][4];
    #pragma unroll
    for (int i = 0; i < 2; i++)
        #pragma unroll
        for (int j = 0; j < 4; j++) acc[i][j] = 0ull;

    for (int tt = 0; tt < TT; tt += 32) {
        #pragma unroll
        for (int i = 0; i < 4; i++) {
            int idx = i * 256 + tid;
            int r = idx >> 5, c = idx & 31;
            qs[r * 34 + c] = q[(size_t)(tt + r) * DD + d0blk + c] * INV_TEMP;
        }
        #pragma unroll
        for (int i = 0; i < 4; i++) {
            int idx = i * 256 + tid;
            int r = idx >> 5, c4 = (idx & 31) * 4;
            *(float4*)&ks[r * 132 + c4] = *(const float4*)&k[(size_t)(tt + r) * DD + c4];
        }
        __syncthreads();
        #pragma unroll 4
        for (int t = 0; t < 32; t++) {
            float2 a = *(float2*)&qs[t * 34 + r0];
            ulonglong2 b0 = *(ulonglong2*)&ks[t * 132 + e0];
            ulonglong2 b1 = *(ulonglong2*)&ks[t * 132 + e0 + 4];
            u64t a0 = pk2(a.x, a.x), a1 = pk2(a.y, a.y);
            fma2(acc[0][0], a0, b0.x); fma2(acc[0][1], a0, b0.y);
            fma2(acc[0][2], a0, b1.x); fma2(acc[0][3], a0, b1.y);
            fma2(acc[1][0], a1, b0.x); fma2(acc[1][1], a1, b0.y);
            fma2(acc[1][2], a1, b1.x); fma2(acc[1][3], a1, b1.y);
        }
        __syncthreads();
    }

    #pragma unroll
    for (int i = 0; i < 2; i++) {
        float x[8];
        up2(acc[i][0], x[0], x[1]); up2(acc[i][1], x[2], x[3]);
        up2(acc[i][2], x[4], x[5]); up2(acc[i][3], x[6], x[7]);
        *(float4*)&Sf[(r0 + i) * 132 + e0]     = make_float4(x[0], x[1], x[2], x[3]);
        *(float4*)&Sf[(r0 + i) * 132 + e0 + 4] = make_float4(x[4], x[5], x[6], x[7]);
    }
    __syncthreads();

    const int lane = tid & 31, w = tid >> 5;
    float* af = attn_f + (size_t)bh * DD * DD;
    #pragma unroll
    for (int rr = 0; rr < 4; rr++) {
        int r = w * 4 + rr;
        float vv[4], mx = -1e30f;
        #pragma unroll
        for (int kk = 0; kk < 4; kk++) {
            vv[kk] = Sf[r * 132 + lane + 32 * kk];
            mx = fmaxf(mx, vv[kk]);
        }
        #pragma unroll
        for (int o = 16; o; o >>= 1) mx = fmaxf(mx, __shfl_xor_sync(~0u, mx, o));
        float ssum = 0.f;
        #pragma unroll
        for (int kk = 0; kk < 4; kk++) { vv[kk] = __expf(vv[kk] - mx); ssum += vv[kk]; }
        #pragma unroll
        for (int o = 16; o; o >>= 1) ssum += __shfl_xor_sync(~0u, ssum, o);
        float iv = 1.0f / ssum;
        #pragma unroll
        for (int kk = 0; kk < 4; kk++)
            af[(size_t)(d0blk + r) * DD + lane + 32 * kk] = vv[kk] * iv;
    }
}

// ---------------------------------------------------------------------------
// Fused time kernel: 64-row tiles, 512 threads, 2 CTAs/SM, software-pipelined:
// iteration c runs MMA1(c) and MMA2(c-1) in the SAME barrier interval
// (E double-buffered), 2 syncs per chunk.
// grid (16, 64), block 512 (16 warps, warp grid 4x4).
// ---------------------------------------------------------------------------
#define SM_Q   0            // Q fp16 TILE128 64 rows, 16K
#define SM_K   16384        // 2 bufs x 16K fp16 (64 t x 128 d)
#define SM_V   49152        // 2 bufs x 16K fp16 (128 d x 64 t)
#define SM_E   81920        // 2 bufs x 8K fp16 (64 t x 64 s)
// tail overlays:
#define SM_TV  0            // tv split-bf16 64 rows: hi @0 16K, lo @16384
#define SM_F   32768        // F^T split-bf16 128 rows: hi @32768 32K, lo @65536
#define SM_RED 98304
#define SM_INV 98560
#define F_SMEM 98816

__global__ void __launch_bounds__(512, 2) fused_time_kernel(
    float* __restrict__ out, float* __restrict__ attn_t) {
    extern __shared__ char sm[];
    const uint32_t sb = smem_u32(sm);
    float* red  = (float*)(sm + SM_RED);
    float* invs = (float*)(sm + SM_INV);

    const int bh = blockIdx.y;
    const int r0 = blockIdx.x * 64;
    const int tid = threadIdx.x;
    const int wid = tid >> 5, lane = tid & 31;
    const int wm = wid & 3, wn = wid >> 2;        // warp grid 4x4
    const int g = lane >> 2, tig = lane & 3;
    const int rA = (lane & 7) + ((lane >> 3) & 1) * 8;
    const int xr = rA & 7, kq = lane >> 4;
    const int fr = wm * 16;

    if (tid < 64) red[tid] = 0.f;

    const unsigned char* qp = g_qf + ((size_t)bh * TT + r0) * 256;
    const unsigned char* kp = g_kf + (size_t)bh * TT * 256;
    const unsigned char* vf = g_vf + (size_t)bh * DD * 2048;
    float* at = attn_t + ((size_t)bh * TT + r0) * TT;

    // prologue groups: G0{Q,K0} G1{V0} G2{K1}
    ld_t128r64_512(sb + SM_Q, qp, 256, tid);
    ld_t128r64_512(sb + SM_K, kp, 256, tid);
    CP_COMMIT();
    ld_t64r128_512(sb + SM_V, vf, 2048, tid);
    CP_COMMIT();
    ld_t128r64_512(sb + SM_K + 16384, kp + 64 * 256, 256, tid);
    CP_COMMIT();

    float rsum[2] = {0, 0};
    float acc2[4][4];
    #pragma unroll
    for (int j = 0; j < 4; j++)
        #pragma unroll
        for (int i = 0; i < 4; i++) acc2[j][i] = 0.f;

    // Pipelined loop: iteration c performs MMA1(c) [c<16] and MMA2(c-1) [c>0].
    // Per-iter commit keeps group math uniform: at iter-c top, K(c) and V(c-1)
    // are covered by wait_group(1) (wait 2 at c==0: only prologue committed).
    for (int c = 0; c <= 16; c++) {
        if (c == 0) { CP_WAIT2(); } else { CP_WAIT1(); }
        __syncthreads();      // sync1: K(c), V(c-1), E(c-1) visible

        float acc1[2][4];
        #pragma unroll
        for (int j = 0; j < 2; j++)
            #pragma unroll
            for (int i = 0; i < 4; i++) acc1[j][i] = 0.f;

        if (c < 16) {
            // ---- MMA1(c): scores 64x64, fp16, warp tile 16x16 ----
            const uint32_t kb = sb + SM_K + (c & 1) * 16384;
            #pragma unroll
            for (int ksi = 0; ksi < 8; ksi++) {
                uint32_t aq[4], bk[4];
                ldsm4(a128(sb + SM_Q, fr, ksi, rA, xr, kq), aq);
                ldsm4(a128(kb, wn * 16, ksi, rA, xr, kq), bk);
                mma16816h(acc1[0], aq, bk[0], bk[2]);
                mma16816h(acc1[1], aq, bk[1], bk[3]);
            }
        }
        if (c > 0) {
            // ---- MMA2(c-1): tv += E(c-1) @ V(c-1), fp16, warp tile 16x32 ----
            const uint32_t vb = sb + SM_V + ((c - 1) & 1) * 16384;
            const uint32_t eb = sb + SM_E + ((c - 1) & 1) * 8192;
            #pragma unroll
            for (int ksi = 0; ksi < 4; ksi++) {
                uint32_t ae[4], b0[4], b1[4];
                ldsm4(a64(eb, fr, ksi, rA, xr, kq), ae);
                {
                    int nr = wn * 32;
                    ldsm4(a64(vb, nr, ksi, rA, xr, kq), b0);
                    ldsm4(a64(vb, nr + 16, ksi, rA, xr, kq), b1);
                }
                mma16816h(acc2[0], ae, b0[0], b0[2]);
                mma16816h(acc2[1], ae, b0[1], b0[3]);
                mma16816h(acc2[2], ae, b1[0], b1[2]);
                mma16816h(acc2[3], ae, b1[1], b1[3]);
            }
        }
        __syncthreads();      // sync2: K(c), V(c-1), E(c-1) consumed by all warps

        // prefetches into buffers whose readers just finished
        if (c < 14)
            ld_t128r64_512(sb + SM_K + (c & 1) * 16384,
                           kp + (size_t)(c + 2) * 64 * 256, 256, tid);
        if (c < 15)
            ld_t64r128_512(sb + SM_V + ((c + 1) & 1) * 16384,
                           vf + (c + 1) * 128, 2048, tid);
        CP_COMMIT();          // exactly one group per iteration (may be empty)

        if (c < 16) {
            // ---- epilogue(c): exp -> unnormalized attn_t + E(c) fp16 smem ----
            const uint32_t eb = sb + SM_E + (c & 1) * 8192;
            const int row = fr + g;
            #pragma unroll
            for (int j = 0; j < 2; j++) {
                float e0 = __expf(acc1[j][0]);
                float e1 = __expf(acc1[j][1]);
                float e2 = __expf(acc1[j][2]);
                float e3 = __expf(acc1[j][3]);
                rsum[0] += e0 + e1;
                rsum[1] += e2 + e3;
                int col = wn * 16 + j * 8 + tig * 2;
                *(float2*)&at[(size_t)row * TT + c * 64 + col]       = make_float2(e0, e1);
                *(float2*)&at[(size_t)(row + 8) * TT + c * 64 + col] = make_float2(e2, e3);
                *(uint32_t*)(sm + (eb - sb) + SWZ64(row, col))     = pack_f16(e0, e1);
                *(uint32_t*)(sm + (eb - sb) + SWZ64(row + 8, col)) = pack_f16(e2, e3);
            }
        }
    }

    // ---- rowsums -> invs ----
    rsum[0] += __shfl_xor_sync(~0u, rsum[0], 1);
    rsum[0] += __shfl_xor_sync(~0u, rsum[0], 2);
    rsum[1] += __shfl_xor_sync(~0u, rsum[1], 1);
    rsum[1] += __shfl_xor_sync(~0u, rsum[1], 2);
    if (tig == 0) {
        atomicAdd(&red[fr + g],     rsum[0]);
        atomicAdd(&red[fr + g + 8], rsum[1]);
    }
    __syncthreads();
    if (tid < 64) invs[tid] = 1.0f / red[tid];
    __syncthreads();

    // ---- F^T loads while we stage tv + normalize attn_t ----
    {
        const unsigned char* fhb = g_fh + (size_t)bh * DD * 256;
        const unsigned char* flb = g_fl + (size_t)bh * DD * 256;
        ld_t128r128_512(sb + SM_F,         fhb, 256, tid);
        ld_t128r128_512(sb + SM_F + 32768, flb, 256, tid);
        CP_COMMIT();
    }
    // stage tv split-bf16 into TV region (64 rows TILE128: hi @SM_TV, lo @+16384)
    {
        const int row = fr + g;
        #pragma unroll
        for (int j = 0; j < 4; j++) {
            int d0v = wn * 32 + j * 8 + tig * 2;
            uint32_t hp, lp;
            split2(acc2[j][0], acc2[j][1], hp, lp);
            *(uint32_t*)(sm + SM_TV + SWZ128(row, d0v)) = hp;
            *(uint32_t*)(sm + SM_TV + 16384 + SWZ128(row, d0v)) = lp;
            split2(acc2[j][2], acc2[j][3], hp, lp);
            *(uint32_t*)(sm + SM_TV + SWZ128(row + 8, d0v)) = hp;
            *(uint32_t*)(sm + SM_TV + 16384 + SWZ128(row + 8, d0v)) = lp;
        }
    }
    // normalize attn_t in place (L2-hot; overlaps with F cp.async)
    {
        float4* at4 = (float4*)at;
        #pragma unroll 4
        for (int it = 0; it < 32; it++) {
            int idx = it * 512 + tid;
            int row = idx >> 8, c4 = idx & 255;
            float iv = invs[row];
            float4 vv = at4[(size_t)row * 256 + c4];
            vv.x *= iv; vv.y *= iv; vv.z *= iv; vv.w *= iv;
            at4[(size_t)row * 256 + c4] = vv;
        }
    }
    CP_WAIT0();
    __syncthreads();

    // ---- GEMM3: out = (tv @ F^T) * inv  (split-bf16) ----
    float acc3[4][4];
    #pragma unroll
    for (int j = 0; j < 4; j++)
        #pragma unroll
        for (int i = 0; i < 4; i++) acc3[j][i] = 0.f;

    #pragma unroll
    for (int ksi = 0; ksi < 8; ksi++) {
        uint32_t ah[4], al[4], b0h[4], b1h[4], b0l[4], b1l[4];
        ldsm4(a128(sb + SM_TV, fr, ksi, rA, xr, kq), ah);
        ldsm4(a128(sb + SM_TV + 16384, fr, ksi, rA, xr, kq), al);
        {
            int nr = wn * 32;
            ldsm4(a128(sb + SM_F, nr, ksi, rA, xr, kq), b0h);
            ldsm4(a128(sb + SM_F, nr + 16, ksi, rA, xr, kq), b1h);
            ldsm4(a128(sb + SM_F + 32768, nr, ksi, rA, xr, kq), b0l);
            ldsm4(a128(sb + SM_F + 32768, nr + 16, ksi, rA, xr, kq), b1l);
        }
        mma16816(acc3[0], ah, b0h[0], b0h[2]);
        mma16816(acc3[1], ah, b0h[1], b0h[3]);
        mma16816(acc3[2], ah, b1h[0], b1h[2]);
        mma16816(acc3[3], ah, b1h[1], b1h[3]);
        mma16816(acc3[0], ah, b0l[0], b0l[2]);
        mma16816(acc3[1], ah, b0l[1], b0l[3]);
        mma16816(acc3[2], ah, b1l[0], b1l[2]);
        mma16816(acc3[3], ah, b1l[1], b1l[3]);
        mma16816(acc3[0], al, b0h[0], b0h[2]);
        mma16816(acc3[1], al, b0h[1], b0h[3]);
        mma16816(acc3[2], al, b1h[0], b1h[2]);
        mma16816(acc3[3], al, b1h[1], b1h[3]);
    }

    float* op = out + ((size_t)bh * TT + r0) * DD;
    {
        const int row = fr + g;
        float iva = invs[row];
        float ivb = invs[row + 8];
        #pragma unroll
        for (int j = 0; j < 4; j++) {
            int e = wn * 32 + j * 8 + tig * 2;
            *(float2*)&op[(size_t)row * DD + e] =
                make_float2(acc3[j][0] * iva, acc3[j][1] * iva);
            *(float2*)&op[(size_t)(row + 8) * DD + e] =
                make_float2(acc3[j][2] * ivb, acc3[j][3] * ivb);
        }
    }
}

// ---------------------------------------------------------------------------
// Launch
// ---------------------------------------------------------------------------
extern "C" void kernel_launch(void* const* d_in, const int* in_sizes, int n_in,
                              void* d_out, int out_size) {
    const float* q_time    = (const float*)d_in[0];
    const float* k_time    = (const float*)d_in[1];
    const float* q_feature = (const float*)d_in[2];
    const float* k_feature = (const float*)d_in[3];
    const float* v         = (const float*)d_in[4];

    float* out    = (float*)d_out;                       // [BH][T][D]
    float* attn_t = out + (size_t)BHN * TT * DD;         // [BH][T][T]
    float* attn_f = attn_t + (size_t)BHN * TT * TT;      // [BH][D][D]

    cudaFuncSetAttribute(fused_time_kernel,
                         cudaFuncAttributeMaxDynamicSharedMemorySize, F_SMEM);

    qk_f16_kernel<<<dim3(8192, 2), 256>>>(q_time, k_time);
    v_f16_T_kernel<<<dim3(32, BHN), 256>>>(v);
    feature_attn_kernel<<<dim3(4, BHN), 256>>>(q_feature, k_feature, attn_f);
    ft_split_T_kernel<<<dim3(4, BHN), 256>>>(attn_f);
    fused_time_kernel<<<dim3(16, BHN), 512, F_SMEM>>>(out, attn_t);
}